// round 12
// baseline (speedup 1.0000x reference)
#include <cuda_runtime.h>
#include <math.h>

#define NUM_TASKS 1000
#define NF 256
#define NH 128
#define BATCH 4096
#define CHUNK 8
#define WARPS_PER_CTA 3
#define CTA_THREADS 96
#define GRID_MLP ((NUM_TASKS + WARPS_PER_CTA - 1) / WARPS_PER_CTA)   // 334

// Scratch (no allocations allowed) — grouping metadata
__device__ int g_off[NUM_TASKS + 1];
__device__ int g_order[BATCH];

// ---------------------------------------------------------------------------
// Fused prep: count + scan + scatter, ONE single-block kernel.
// ---------------------------------------------------------------------------
__global__ __launch_bounds__(1024) void prep_k(const int* __restrict__ task_ids, int n) {
    __shared__ int cnt[NUM_TASKS];
    __shared__ int sc[1024];
    int tid = threadIdx.x;

    for (int i = tid; i < NUM_TASKS; i += 1024) cnt[i] = 0;
    __syncthreads();
    for (int i = tid; i < n; i += 1024) atomicAdd(&cnt[task_ids[i]], 1);
    __syncthreads();

    sc[tid] = (tid < NUM_TASKS) ? cnt[tid] : 0;
    __syncthreads();
    for (int d = 1; d < 1024; d <<= 1) {
        int v = (tid >= d) ? sc[tid - d] : 0;
        __syncthreads();
        sc[tid] += v;
        __syncthreads();
    }
    if (tid < NUM_TASKS) {
        g_off[tid + 1] = sc[tid];
        if (tid == 0) g_off[0] = 0;
        cnt[tid] = (tid == 0) ? 0 : sc[tid - 1];
    }
    __syncthreads();

    for (int i = tid; i < n; i += 1024) {
        int p = atomicAdd(&cnt[task_ids[i]], 1);
        g_order[p] = i;
    }
}

__device__ __forceinline__ float gelu_exact(float h) {
    return 0.5f * h * (1.0f + erff(h * 0.70710678118654752f));
}

// ---------------------------------------------------------------------------
// One pass over W for up to SS samples, executed by ONE warp, no block sync.
// Lane owns hidden cols 4*lane..4*lane+3 (float4 accumulators).
// Pad slots (s >= S) replicate sample 0; computed but never stored.
// ---------------------------------------------------------------------------
template<int SS>
__device__ __forceinline__ void task_pass(
    int base, int S, int lane,
    const float* __restrict__ x, const float4* __restrict__ Wv,
    float4 b1, float4 w2, float b2,
    float (*__restrict__ swx)[NF], float* __restrict__ out)
{
    int src = base + ((lane < S) ? lane : 0);
    int my_ord = __ldg(&g_order[src]);         // lane s holds sample s's row id

    // Stage x rows: per sample, 2 coalesced LDG.128 per lane (512B x 2)
    #pragma unroll
    for (int s = 0; s < SS; s++) {
        int ord = __shfl_sync(0xffffffffu, my_ord, s);
        const float4* xr = (const float4*)(x + (size_t)ord * NF);
        ((float4*)swx[s])[lane]      = __ldg(&xr[lane]);
        ((float4*)swx[s])[lane + 32] = __ldg(&xr[lane + 32]);
    }
    __syncwarp();

    float4 acc[SS];
    #pragma unroll
    for (int s = 0; s < SS; s++) acc[s] = make_float4(0.f, 0.f, 0.f, 0.f);

    // Continuous 256-row LDG.128 stream, zero barriers
    #pragma unroll 8
    for (int r = 0; r < NF; r++) {
        float4 wv = __ldg(&Wv[(size_t)r * (NH / 4)]);
        #pragma unroll
        for (int s = 0; s < SS; s++) {
            float xs = swx[s][r];               // smem broadcast
            acc[s].x = fmaf(xs, wv.x, acc[s].x);
            acc[s].y = fmaf(xs, wv.y, acc[s].y);
            acc[s].z = fmaf(xs, wv.z, acc[s].z);
            acc[s].w = fmaf(xs, wv.w, acc[s].w);
        }
    }

    // Epilogue: gelu + weighted sum over this lane's 4 cols, warp reduce
    float res = 0.f;
    #pragma unroll
    for (int s = 0; s < SS; s++) {
        float p = gelu_exact(acc[s].x + b1.x) * w2.x
                + gelu_exact(acc[s].y + b1.y) * w2.y
                + gelu_exact(acc[s].z + b1.z) * w2.z
                + gelu_exact(acc[s].w + b1.w) * w2.w;
        p += __shfl_xor_sync(0xffffffffu, p, 16);
        p += __shfl_xor_sync(0xffffffffu, p, 8);
        p += __shfl_xor_sync(0xffffffffu, p, 4);
        p += __shfl_xor_sync(0xffffffffu, p, 2);
        p += __shfl_xor_sync(0xffffffffu, p, 1);
        if (lane == s) res = p;
    }
    if (lane < S) out[my_ord] = res + b2;
    __syncwarp();   // protect swx before a possible next pass restages it
}

// One WARP per task: grid 334 x 96 threads = 1002 warps, static assignment.
__global__ __launch_bounds__(CTA_THREADS) void mlp_k(
    const float* __restrict__ x,
    const float* __restrict__ l1_emb,
    const float* __restrict__ l1_bias,
    const float* __restrict__ l2_emb,
    const float* __restrict__ l2_bias,
    float* __restrict__ out)
{
    int wid  = threadIdx.x >> 5;
    int lane = threadIdx.x & 31;
    int t    = blockIdx.x * WARPS_PER_CTA + wid;

    __shared__ float sx[WARPS_PER_CTA][CHUNK][NF];   // 24 KB

    if (t >= NUM_TASKS) return;
    int beg = g_off[t];
    int n   = g_off[t + 1] - beg;
    if (n == 0) return;

    const float4* Wv = (const float4*)(l1_emb + (size_t)t * (NF * NH)) + lane;
    float4 b1 = __ldg((const float4*)(l1_bias + (size_t)t * NH) + lane);
    float4 w2 = __ldg((const float4*)(l2_emb + (size_t)t * NH) + lane);
    float  b2 = __ldg(&l2_bias[t]);

    int pos = beg, rem = n;
    while (rem > 0) {
        if (rem > 4) {
            task_pass<8>(pos, min(rem, 8), lane, x, Wv, b1, w2, b2, sx[wid], out);
            pos += 8; rem -= 8;
        } else {
            task_pass<4>(pos, rem, lane, x, Wv, b1, w2, b2, sx[wid], out);
            rem = 0;
        }
    }
}

extern "C" void kernel_launch(void* const* d_in, const int* in_sizes, int n_in,
                              void* d_out, int out_size) {
    const float* x       = (const float*)d_in[0];
    const int*   task_id = (const int*)  d_in[1];
    const float* l1_emb  = (const float*)d_in[2];
    const float* l1_bias = (const float*)d_in[3];
    const float* l2_emb  = (const float*)d_in[4];
    const float* l2_bias = (const float*)d_in[5];
    float* out = (float*)d_out;

    int nb = in_sizes[1];  // BATCH

    prep_k<<<1, 1024>>>(task_id, nb);
    mlp_k<<<GRID_MLP, CTA_THREADS>>>(x, l1_emb, l1_bias, l2_emb, l2_bias, out);
}

// round 15
// speedup vs baseline: 1.1200x; 1.1200x over previous
#include <cuda_runtime.h>
#include <math.h>
#include <stdint.h>

#define NUM_TASKS 1000
#define NF 256
#define NH 128
#define BATCH 4096
#define NSTAGE 4
#define TILE_ROWS 32
#define TILE_BYTES (TILE_ROWS * NH * 4)      // 16384
#define NTILES (NF / TILE_ROWS)              // 8
#define XPITCH 12                            // padded x-transpose row (floats)

// smem layout (bytes)
#define WS_OFF   0
#define XT_OFF   (NSTAGE * TILE_BYTES)                   // 65536
#define HP_OFF   (XT_OFF + NF * XPITCH * 4)              // 77824
#define SRED_OFF (HP_OFF + 8 * 8 * NH * 4)               // 110592
#define SIDX_OFF (SRED_OFF + 4 * 8 * 4)                  // 110720
#define MB_OFF   (SIDX_OFF + 64)                         // 110784 (8-aligned)
#define SMEM_TOTAL (MB_OFF + 8 * 8)                      // 110848

__device__ int g_off[NUM_TASKS + 1];
__device__ int g_order[BATCH];

// ---------------------------------------------------------------------------
__global__ __launch_bounds__(1024) void prep_k(const int* __restrict__ task_ids, int n) {
    __shared__ int cnt[NUM_TASKS];
    __shared__ int sc[1024];
    int tid = threadIdx.x;

    for (int i = tid; i < NUM_TASKS; i += 1024) cnt[i] = 0;
    __syncthreads();
    for (int i = tid; i < n; i += 1024) atomicAdd(&cnt[task_ids[i]], 1);
    __syncthreads();

    sc[tid] = (tid < NUM_TASKS) ? cnt[tid] : 0;
    __syncthreads();
    for (int d = 1; d < 1024; d <<= 1) {
        int v = (tid >= d) ? sc[tid - d] : 0;
        __syncthreads();
        sc[tid] += v;
        __syncthreads();
    }
    if (tid < NUM_TASKS) {
        g_off[tid + 1] = sc[tid];
        if (tid == 0) g_off[0] = 0;
        cnt[tid] = (tid == 0) ? 0 : sc[tid - 1];
    }
    __syncthreads();

    for (int i = tid; i < n; i += 1024) {
        int p = atomicAdd(&cnt[task_ids[i]], 1);
        g_order[p] = i;
    }
}

__device__ __forceinline__ float gelu_exact(float h) {
    return 0.5f * h * (1.0f + erff(h * 0.70710678118654752f));
}

__device__ __forceinline__ uint32_t s2u(const void* p) {
    uint32_t a;
    asm("{ .reg .u64 t; cvta.to.shared.u64 t, %1; cvt.u32.u64 %0, t; }" : "=r"(a) : "l"(p));
    return a;
}
#define MB_INIT(a, c)  asm volatile("mbarrier.init.shared.b64 [%0], %1;" :: "r"(a), "r"(c) : "memory")
#define MB_TX(a, b)    asm volatile("mbarrier.arrive.expect_tx.shared.b64 _, [%0], %1;" :: "r"(a), "r"(b) : "memory")
#define MB_ARRIVE(a)   asm volatile("mbarrier.arrive.shared.b64 _, [%0];" :: "r"(a) : "memory")
#define BULK_G2S(dst, src, nbytes, mbar) \
    asm volatile("cp.async.bulk.shared::cluster.global.mbarrier::complete_tx::bytes [%0], [%1], %2, [%3];" \
        :: "r"(dst), "l"(src), "r"(nbytes), "r"(mbar) : "memory")

__device__ __forceinline__ void mb_wait(uint32_t addr, int parity) {
    uint32_t done;
    asm volatile("{\n\t.reg .pred p;\n\tmbarrier.try_wait.parity.acquire.cta.shared::cta.b64 p, [%1], %2;\n\tselp.b32 %0,1,0,p;\n\t}"
        : "=r"(done) : "r"(addr), "r"(parity) : "memory");
    while (!done) {
        asm volatile("{\n\t.reg .pred p;\n\tmbarrier.try_wait.parity.acquire.cta.shared::cta.b64 p, [%1], %2, 0x989680;\n\tselp.b32 %0,1,0,p;\n\t}"
            : "=r"(done) : "r"(addr), "r"(parity) : "memory");
    }
}

// One CTA per task, 256 threads. W1 streamed via 4-stage cp.async.bulk pipeline.
__global__ __launch_bounds__(256) void mlp_k(
    const float* __restrict__ x,
    const float* __restrict__ l1_emb,
    const float* __restrict__ l1_bias,
    const float* __restrict__ l2_emb,
    const float* __restrict__ l2_bias,
    float* __restrict__ out)
{
    extern __shared__ char smem[];
    int t = blockIdx.x;
    int beg = g_off[t];
    int n   = g_off[t + 1] - beg;
    if (n == 0) return;

    int tid  = threadIdx.x;
    int wg   = tid >> 5;
    int lane = tid & 31;
    int j    = tid & 127;

    float* ws    = (float*)(smem + WS_OFF);       // [NSTAGE][32][128]
    float* swxt  = (float*)(smem + XT_OFF);       // [NF][XPITCH], sample-major inner
    float* hpart = (float*)(smem + HP_OFF);       // [(g*8+s)*NH + col]
    float* sred  = (float*)(smem + SRED_OFF);     // [w*8+s]
    int*   sidx  = (int*)  (smem + SIDX_OFF);
    uint32_t smb  = s2u(smem);
    uint32_t mb_full  = smb + MB_OFF;             // 4 x 8B
    uint32_t mb_empty = smb + MB_OFF + 32;
    uint32_t ws_u = smb + WS_OFF;

    const char* Wt = (const char*)(l1_emb + (size_t)t * (NF * NH));
    float b1 = l1_bias[t * NH + j];
    float w2 = l2_emb[t * NH + j];
    float b2 = __ldg(&l2_bias[t]);

    if (tid == 0) {
        #pragma unroll
        for (int i = 0; i < NSTAGE; i++) {
            MB_INIT(mb_full + 8 * i, 1);
            MB_INIT(mb_empty + 8 * i, 8);
        }
    }
    __syncthreads();
    if (tid == 0) asm volatile("fence.proxy.async.shared::cta;" ::: "memory");

    // pass count / total tiles
    int npass = 0;
    for (int r = n; r > 0;) { if (r > 4) r -= 8; else r = 0; npass++; }
    int total_tiles = npass * NTILES;

    int issued = 0;
    int p_st = 0, p_ph = 1;                       // producer empty-cursor, phase starts 1
    if (tid == 0) {
        int pro = min(NSTAGE, total_tiles);
        for (int i = 0; i < pro; i++) {
            mb_wait(mb_empty + 8 * p_st, p_ph);   // passes immediately (phase 1)
            MB_TX(mb_full + 8 * p_st, TILE_BYTES);
            BULK_G2S(ws_u + p_st * TILE_BYTES, Wt + (size_t)(i % NTILES) * TILE_BYTES,
                     TILE_BYTES, mb_full + 8 * p_st);
            issued++;
            if (++p_st == NSTAGE) { p_st = 0; p_ph ^= 1; }
        }
    }

    int c_st = 0, c_ph = 0;                       // consumer full-cursor
    int pos = beg, rem = n;
    while (rem > 0) {
        int ssr = (rem > 4) ? 8 : 4;              // pass width (uniform)
        int S   = (rem > 4) ? min(rem, 8) : rem;  // live samples

        // Stage x transposed: swxt[f][s]; f = tid (coalesced per sample)
        for (int s = 0; s < ssr; s++) {
            int src = pos + ((s < S) ? s : 0);
            int ord = __ldg(&g_order[src]);
            if (tid == s) sidx[s] = ord;
            swxt[tid * XPITCH + s] = __ldg(&x[(size_t)ord * NF + tid]);
        }
        __syncthreads();

        float4 acc[8];
        #pragma unroll
        for (int s = 0; s < 8; s++) acc[s] = make_float4(0.f, 0.f, 0.f, 0.f);

        for (int tp = 0; tp < NTILES; tp++) {
            mb_wait(mb_full + 8 * c_st, c_ph);

            const float* wst = ws + c_st * (TILE_ROWS * NH);
            int rb = tp * TILE_ROWS + 4 * wg;     // this warp's 4 rows (global f index)
            int rl = 4 * wg;                      // row within tile
            #pragma unroll
            for (int i = 0; i < 4; i++) {
                float4 wv = *(const float4*)&wst[(rl + i) * NH + lane * 4];
                const float* xr = &swxt[(rb + i) * XPITCH];
                float4 xa = *(const float4*)xr;
                acc[0].x = fmaf(xa.x, wv.x, acc[0].x); acc[0].y = fmaf(xa.x, wv.y, acc[0].y);
                acc[0].z = fmaf(xa.x, wv.z, acc[0].z); acc[0].w = fmaf(xa.x, wv.w, acc[0].w);
                acc[1].x = fmaf(xa.y, wv.x, acc[1].x); acc[1].y = fmaf(xa.y, wv.y, acc[1].y);
                acc[1].z = fmaf(xa.y, wv.z, acc[1].z); acc[1].w = fmaf(xa.y, wv.w, acc[1].w);
                acc[2].x = fmaf(xa.z, wv.x, acc[2].x); acc[2].y = fmaf(xa.z, wv.y, acc[2].y);
                acc[2].z = fmaf(xa.z, wv.z, acc[2].z); acc[2].w = fmaf(xa.z, wv.w, acc[2].w);
                acc[3].x = fmaf(xa.w, wv.x, acc[3].x); acc[3].y = fmaf(xa.w, wv.y, acc[3].y);
                acc[3].z = fmaf(xa.w, wv.z, acc[3].z); acc[3].w = fmaf(xa.w, wv.w, acc[3].w);
                if (ssr == 8) {
                    float4 xb = *(const float4*)(xr + 4);
                    acc[4].x = fmaf(xb.x, wv.x, acc[4].x); acc[4].y = fmaf(xb.x, wv.y, acc[4].y);
                    acc[4].z = fmaf(xb.x, wv.z, acc[4].z); acc[4].w = fmaf(xb.x, wv.w, acc[4].w);
                    acc[5].x = fmaf(xb.y, wv.x, acc[5].x); acc[5].y = fmaf(xb.y, wv.y, acc[5].y);
                    acc[5].z = fmaf(xb.y, wv.z, acc[5].z); acc[5].w = fmaf(xb.y, wv.w, acc[5].w);
                    acc[6].x = fmaf(xb.z, wv.x, acc[6].x); acc[6].y = fmaf(xb.z, wv.y, acc[6].y);
                    acc[6].z = fmaf(xb.z, wv.z, acc[6].z); acc[6].w = fmaf(xb.z, wv.w, acc[6].w);
                    acc[7].x = fmaf(xb.w, wv.x, acc[7].x); acc[7].y = fmaf(xb.w, wv.y, acc[7].y);
                    acc[7].z = fmaf(xb.w, wv.z, acc[7].z); acc[7].w = fmaf(xb.w, wv.w, acc[7].w);
                }
            }

            __syncwarp();
            if (lane == 0) MB_ARRIVE(mb_empty + 8 * c_st);
            if (++c_st == NSTAGE) { c_st = 0; c_ph ^= 1; }

            if (tid == 0 && issued < total_tiles) {
                mb_wait(mb_empty + 8 * p_st, p_ph);
                MB_TX(mb_full + 8 * p_st, TILE_BYTES);
                BULK_G2S(ws_u + p_st * TILE_BYTES, Wt + (size_t)(issued % NTILES) * TILE_BYTES,
                         TILE_BYTES, mb_full + 8 * p_st);
                issued++;
                if (++p_st == NSTAGE) { p_st = 0; p_ph ^= 1; }
            }
        }

        // combine partials
        for (int s = 0; s < ssr; s++)
            *(float4*)&hpart[(wg * 8 + s) * NH + lane * 4] = acc[s];
        __syncthreads();

        if (tid < NH) {
            int l2l = tid & 31, l2w = tid >> 5;
            #pragma unroll 4
            for (int s = 0; s < ssr; s++) {
                float h = b1;
                #pragma unroll
                for (int g = 0; g < 8; g++) h += hpart[(g * 8 + s) * NH + j];
                float v = gelu_exact(h) * w2;
                v += __shfl_xor_sync(0xffffffffu, v, 16);
                v += __shfl_xor_sync(0xffffffffu, v, 8);
                v += __shfl_xor_sync(0xffffffffu, v, 4);
                v += __shfl_xor_sync(0xffffffffu, v, 2);
                v += __shfl_xor_sync(0xffffffffu, v, 1);
                if (l2l == 0) sred[l2w * 8 + s] = v;
            }
        }
        __syncthreads();

        if (tid < S) {
            float sum = sred[tid] + sred[8 + tid] + sred[16 + tid] + sred[24 + tid];
            out[sidx[tid]] = sum + b2;
        }
        __syncthreads();

        if (rem > 4) { pos += 8; rem -= 8; } else { rem = 0; }
    }
}

extern "C" void kernel_launch(void* const* d_in, const int* in_sizes, int n_in,
                              void* d_out, int out_size) {
    const float* x       = (const float*)d_in[0];
    const int*   task_id = (const int*)  d_in[1];
    const float* l1_emb  = (const float*)d_in[2];
    const float* l1_bias = (const float*)d_in[3];
    const float* l2_emb  = (const float*)d_in[4];
    const float* l2_bias = (const float*)d_in[5];
    float* out = (float*)d_out;

    int nb = in_sizes[1];  // BATCH

    // Unconditional (no static guards): idempotent, host-side, capture-safe.
    cudaFuncSetAttribute(mlp_k, cudaFuncAttributeMaxDynamicSharedMemorySize, SMEM_TOTAL);

    prep_k<<<1, 1024>>>(task_id, nb);
    mlp_k<<<NUM_TASKS, 256, SMEM_TOTAL>>>(x, l1_emb, l1_bias, l2_emb, l2_bias, out);
}

// round 16
// speedup vs baseline: 1.4350x; 1.2813x over previous
#include <cuda_runtime.h>
#include <math.h>

#define NUM_TASKS 1000
#define NF 256
#define NH 128
#define BATCH 4096
#define XPITCH 12   // transposed-x row pitch (floats): 48B, 16B-aligned float4 reads

__device__ int g_off[NUM_TASKS + 1];
__device__ int g_order[BATCH];

// ---------------------------------------------------------------------------
// Fused prep: count + scan + scatter, ONE single-block kernel.
// ---------------------------------------------------------------------------
__global__ __launch_bounds__(1024) void prep_k(const int* __restrict__ task_ids, int n) {
    __shared__ int cnt[NUM_TASKS];
    __shared__ int sc[1024];
    int tid = threadIdx.x;

    for (int i = tid; i < NUM_TASKS; i += 1024) cnt[i] = 0;
    __syncthreads();
    for (int i = tid; i < n; i += 1024) atomicAdd(&cnt[task_ids[i]], 1);
    __syncthreads();

    sc[tid] = (tid < NUM_TASKS) ? cnt[tid] : 0;
    __syncthreads();
    for (int d = 1; d < 1024; d <<= 1) {
        int v = (tid >= d) ? sc[tid - d] : 0;
        __syncthreads();
        sc[tid] += v;
        __syncthreads();
    }
    if (tid < NUM_TASKS) {
        g_off[tid + 1] = sc[tid];
        if (tid == 0) g_off[0] = 0;
        cnt[tid] = (tid == 0) ? 0 : sc[tid - 1];
    }
    __syncthreads();

    for (int i = tid; i < n; i += 1024) {
        int p = atomicAdd(&cnt[task_ids[i]], 1);
        g_order[p] = i;
    }
}

__device__ __forceinline__ float gelu_exact(float h) {
    return 0.5f * h * (1.0f + erff(h * 0.70710678118654752f));
}

// ---------------------------------------------------------------------------
// Chunk body. 8 warp-groups; wg streams its 32 contiguous W rows via LDG.128,
// fully unrolled so ptxas software-pipelines to deep MLP under a 128-reg budget.
// x read from transposed smem: 2 LDS.128 broadcasts per row.
// Pad slots (s >= S) replicate sample 0; computed but never stored.
// ---------------------------------------------------------------------------
template<int SS>
__device__ __forceinline__ void do_chunk(
    int base, int S, int tid, int wg, int lane, int j,
    const float* __restrict__ x, const float* __restrict__ W,
    float b1, float w2, float b2,
    float* __restrict__ swxt, float (*hpart)[8][NH], int* sidx, float (*sred)[8],
    float* __restrict__ out)
{
    // Stage x transposed: swxt[f*XPITCH + s]; f = tid (coalesced LDG per sample)
    #pragma unroll
    for (int s = 0; s < SS; s++) {
        int src = base + ((s < S) ? s : 0);
        int ord = __ldg(&g_order[src]);
        if (tid == s) sidx[s] = ord;
        swxt[tid * XPITCH + s] = __ldg(&x[(size_t)ord * NF + tid]);
    }
    __syncthreads();

    const float4* __restrict__ Wv =
        (const float4*)(W + (size_t)(wg * 32) * NH) + lane;   // row stride 32 float4

    float4 acc[SS];
    #pragma unroll
    for (int s = 0; s < SS; s++) acc[s] = make_float4(0.f, 0.f, 0.f, 0.f);

    #pragma unroll
    for (int r = 0; r < 32; r++) {
        float4 wv = __ldg(&Wv[r * 32]);                       // LDG.128
        const float4* xp = (const float4*)&swxt[(wg * 32 + r) * XPITCH];
        float4 xa = xp[0];                                    // samples 0..3 (broadcast)
        acc[0].x = fmaf(xa.x, wv.x, acc[0].x); acc[0].y = fmaf(xa.x, wv.y, acc[0].y);
        acc[0].z = fmaf(xa.x, wv.z, acc[0].z); acc[0].w = fmaf(xa.x, wv.w, acc[0].w);
        acc[1].x = fmaf(xa.y, wv.x, acc[1].x); acc[1].y = fmaf(xa.y, wv.y, acc[1].y);
        acc[1].z = fmaf(xa.y, wv.z, acc[1].z); acc[1].w = fmaf(xa.y, wv.w, acc[1].w);
        acc[2].x = fmaf(xa.z, wv.x, acc[2].x); acc[2].y = fmaf(xa.z, wv.y, acc[2].y);
        acc[2].z = fmaf(xa.z, wv.z, acc[2].z); acc[2].w = fmaf(xa.z, wv.w, acc[2].w);
        acc[3].x = fmaf(xa.w, wv.x, acc[3].x); acc[3].y = fmaf(xa.w, wv.y, acc[3].y);
        acc[3].z = fmaf(xa.w, wv.z, acc[3].z); acc[3].w = fmaf(xa.w, wv.w, acc[3].w);
        if (SS == 8) {
            float4 xb = xp[1];                                // samples 4..7
            acc[4].x = fmaf(xb.x, wv.x, acc[4].x); acc[4].y = fmaf(xb.x, wv.y, acc[4].y);
            acc[4].z = fmaf(xb.x, wv.z, acc[4].z); acc[4].w = fmaf(xb.x, wv.w, acc[4].w);
            acc[5].x = fmaf(xb.y, wv.x, acc[5].x); acc[5].y = fmaf(xb.y, wv.y, acc[5].y);
            acc[5].z = fmaf(xb.y, wv.z, acc[5].z); acc[5].w = fmaf(xb.y, wv.w, acc[5].w);
            acc[6].x = fmaf(xb.z, wv.x, acc[6].x); acc[6].y = fmaf(xb.z, wv.y, acc[6].y);
            acc[6].z = fmaf(xb.z, wv.z, acc[6].z); acc[6].w = fmaf(xb.z, wv.w, acc[6].w);
            acc[7].x = fmaf(xb.w, wv.x, acc[7].x); acc[7].y = fmaf(xb.w, wv.y, acc[7].y);
            acc[7].z = fmaf(xb.w, wv.z, acc[7].z); acc[7].w = fmaf(xb.w, wv.w, acc[7].w);
        }
    }

    #pragma unroll
    for (int s = 0; s < SS; s++)
        *(float4*)&hpart[wg][s][lane * 4] = acc[s];
    __syncthreads();

    if (tid < NH) {
        int l2l = tid & 31, l2w = tid >> 5;
        #pragma unroll
        for (int s = 0; s < SS; s++) {
            float h = b1;
            #pragma unroll
            for (int g = 0; g < 8; g++) h += hpart[g][s][j];
            float v = gelu_exact(h) * w2;
            v += __shfl_xor_sync(0xffffffffu, v, 16);
            v += __shfl_xor_sync(0xffffffffu, v, 8);
            v += __shfl_xor_sync(0xffffffffu, v, 4);
            v += __shfl_xor_sync(0xffffffffu, v, 2);
            v += __shfl_xor_sync(0xffffffffu, v, 1);
            if (l2l == 0) sred[l2w][s] = v;
        }
    }
    __syncthreads();

    if (tid < S) {
        float sum = sred[0][tid] + sred[1][tid] + sred[2][tid] + sred[3][tid];
        out[sidx[tid]] = sum + b2;
    }
    __syncthreads();
}

// One CTA per task, 256 threads, 2 CTAs/SM (128-reg budget for deep LDG pipelining).
__global__ __launch_bounds__(256, 2) void mlp_k(
    const float* __restrict__ x,
    const float* __restrict__ l1_emb,
    const float* __restrict__ l1_bias,
    const float* __restrict__ l2_emb,
    const float* __restrict__ l2_bias,
    float* __restrict__ out)
{
    int t = blockIdx.x;
    int beg = g_off[t];
    int n   = g_off[t + 1] - beg;
    if (n == 0) return;

    int tid  = threadIdx.x;
    int wg   = tid >> 5;
    int lane = tid & 31;
    int j    = tid & 127;

    const float* __restrict__ W = l1_emb + (size_t)t * (NF * NH);
    float b1 = l1_bias[t * NH + j];
    float w2 = l2_emb[t * NH + j];
    float b2 = __ldg(&l2_bias[t]);

    __shared__ float swxt[NF * XPITCH];       // 12 KB transposed x
    __shared__ float hpart[8][8][NH];         // 32 KB
    __shared__ int   sidx[8];
    __shared__ float sred[4][8];

    int pos = beg, rem = n;
    while (rem > 0) {
        if (rem > 4) {
            do_chunk<8>(pos, min(rem, 8), tid, wg, lane, j, x, W, b1, w2, b2,
                        swxt, hpart, sidx, sred, out);
            pos += 8; rem -= 8;
        } else {
            do_chunk<4>(pos, rem, tid, wg, lane, j, x, W, b1, w2, b2,
                        swxt, hpart, sidx, sred, out);
            rem = 0;
        }
    }
}

extern "C" void kernel_launch(void* const* d_in, const int* in_sizes, int n_in,
                              void* d_out, int out_size) {
    const float* x       = (const float*)d_in[0];
    const int*   task_id = (const int*)  d_in[1];
    const float* l1_emb  = (const float*)d_in[2];
    const float* l1_bias = (const float*)d_in[3];
    const float* l2_emb  = (const float*)d_in[4];
    const float* l2_bias = (const float*)d_in[5];
    float* out = (float*)d_out;

    int nb = in_sizes[1];  // BATCH

    prep_k<<<1, 1024>>>(task_id, nb);
    mlp_k<<<NUM_TASKS, 256>>>(x, l1_emb, l1_bias, l2_emb, l2_bias, out);
}